// round 16
// baseline (speedup 1.0000x reference)
#include <cuda_runtime.h>
#include <cuda_bf16.h>

#define T_LEN   8192
#define F_DIM   80
#define BINS    24
#define NT      1024
#define PER     (T_LEN / NT)     // 8
#define NW      (NT / 32)        // 32 warps
#define HORIZON 0.35f

__global__ __launch_bounds__(NT) void rhythm_kernel(
    const float* __restrict__ feat,
    const int*   __restrict__ mask,
    const float* __restrict__ phase,
    float*       __restrict__ out,
    const int    ws)
{
    const int b   = blockIdx.x;
    const int B   = gridDim.x;
    const int tid = threadIdx.x;

    __shared__ float s_trace[BINS * F_DIM];  // 7.5 KB
    __shared__ int   s_left[BINS], s_right[BINS];
    __shared__ float s_alpha[BINS];
    __shared__ int   s_cstar[BINS];
    __shared__ int   s_wsum[NW];             // inclusive-scanned warp sums
    __shared__ int   s_wrises[NW];

    // ---- blocked GMEM load: each thread reads its own 8 mask values ----
    const int* mb   = mask + (size_t)b * T_LEN;
    const int  base = tid * PER;
    int m[PER];
    {
        const int4* p4 = (const int4*)(mb + base);
        #pragma unroll
        for (int q = 0; q < PER / 4; q++) {
            int4 w = p4[q];
            m[4 * q + 0] = w.x; m[4 * q + 1] = w.y;
            m[4 * q + 2] = w.z; m[4 * q + 3] = w.w;
        }
    }
    const int prev0 = (tid == 0) ? 0 : mb[base - 1];

    // ---- rises + local inclusive scan (registers only) ----
    int v[PER];
    const int lane = tid & 31, warp = tid >> 5;
    int run;
    {
        int prev = prev0, rises = 0, r0 = 0;
        #pragma unroll
        for (int k = 0; k < PER; k++) {
            rises += (m[k] == 1 && prev == 0);
            prev   = m[k];
            r0    += m[k];
            v[k]   = r0;
        }
        run = r0;
        #pragma unroll
        for (int o = 16; o; o >>= 1) rises += __shfl_down_sync(0xffffffffu, rises, o);
        if (lane == 0) s_wrises[warp] = rises;
    }
    // warp-level inclusive scan of per-thread sums
    int x = run;
    #pragma unroll
    for (int o = 1; o < 32; o <<= 1) {
        int y = __shfl_up_sync(0xffffffffu, x, o);
        if (lane >= o) x += y;
    }
    if (lane == 31) s_wsum[warp] = x;
    __syncthreads();
    if (tid < NW) {
        int xx = s_wsum[tid];
        #pragma unroll
        for (int o = 1; o < NW; o <<= 1) {
            int y = __shfl_up_sync(0xffffffffu, xx, o);
            if (tid >= o) xx += y;
        }
        s_wsum[tid] = xx;                    // inclusive warp-prefix sums
    }
    __syncthreads();

    const int prefix = ((warp == 0) ? 0 : s_wsum[warp - 1]) + (x - run); // exclusive
    const int total  = s_wsum[NW - 1];
    const float maxtot      = fmaxf((float)total, 1.0f);
    const bool  use_uniform = (total <= 0);
    // XLA AlgebraicSimplifier: divide -> multiply by hoisted IEEE reciprocal.
    const float recip   = __fdiv_rn(1.0f, maxtot);
    const float delta_t = __fdiv_rn(1.0f, (float)(BINS - 1));

    // ---- searchsorted without the cumsum array ----
    // p[k] = RN(csum[k]*recip) is monotone in csum[k], so
    //   right_i = first k with csum[k] >= c*_i,
    //   c*_i = min{ c : RN(c*recip) >= t_i }   (scan +/-3 window around ceil).
    // csum steps by 0/1 => csum[right-1]=c*-1, csum[right]=c* exactly.
    if (!use_uniform) {
        #pragma unroll 1
        for (int i = 0; i < BINS; i++) {
            const float target = (i == BINS - 1) ? 1.0f
                               : __fmul_rn((float)i, delta_t);
            int cb = (int)ceilf(__fmul_rn(target, maxtot)) - 3;
            if (cb < 0) cb = 0;
            int cstar = cb + 7;
            #pragma unroll 1
            for (int c = cb; c <= cb + 6; c++) {
                if (__fmul_rn((float)c, recip) >= target) { cstar = c; break; }
            }
            if (tid == i) {
                s_cstar[i] = cstar;
                if (cstar <= 0)          s_right[i] = 0;      // sole writer
                else if (cstar > total)  s_right[i] = T_LEN;  // sole writer
            }
            // unique owner writes when 1 <= c* <= total
            if (cstar >= 1 && cstar <= total &&
                prefix < cstar && cstar <= prefix + run) {
                const int need = cstar - prefix;
                int pos = PER - 1;
                #pragma unroll
                for (int k = PER - 1; k >= 0; k--) if (v[k] >= need) pos = k;
                s_right[i] = base + pos;
            }
        }
    }
    __syncthreads();

    // ---- per-bin left/right/alpha (24 threads) ----
    if (tid < BINS) {
        const float target = (tid == BINS - 1) ? 1.0f
                           : __fmul_rn((float)tid, delta_t);
        int right, l, rc;
        float a;
        if (use_uniform) {
            const float delta_u = __fdiv_rn(1.0f, (float)(T_LEN - 1));
            int lo = 0, hi = T_LEN;
            while (lo < hi) {
                int   mid = (lo + hi) >> 1;
                float p   = (mid == T_LEN - 1) ? 1.0f
                          : __fmul_rn((float)mid, delta_u);
                if (p >= target) hi = mid; else lo = mid + 1;
            }
            right = lo;
            l  = min(max(right - 1, 0), T_LEN - 1);
            rc = min(right, T_LEN - 1);
            if (right <= 0)          { l = 0;         rc = 0;         a = 0.0f; }
            else if (right >= T_LEN) { l = T_LEN - 1; rc = T_LEN - 1; a = 0.0f; }
            else {
                float lp = (l  == T_LEN - 1) ? 1.0f : __fmul_rn((float)l,  delta_u);
                float rp = (rc == T_LEN - 1) ? 1.0f : __fmul_rn((float)rc, delta_u);
                float denom = fmaxf(fabsf(__fadd_rn(rp, -lp)), 1e-6f);
                a = fminf(fmaxf(__fdiv_rn(__fadd_rn(target, -lp), denom), 0.0f), 1.0f);
            }
        } else {
            right = s_right[tid];
            const int cstar = s_cstar[tid];
            if (right <= 0)          { l = 0;         rc = 0;         a = 0.0f; }
            else if (right >= T_LEN) { l = T_LEN - 1; rc = T_LEN - 1; a = 0.0f; }
            else {
                l  = right - 1;
                rc = right;
                float lp = __fmul_rn((float)(cstar - 1), recip);
                float rp = __fmul_rn((float)cstar,       recip);
                float denom = fmaxf(fabsf(__fadd_rn(rp, -lp)), 1e-6f);
                a = fminf(fmaxf(__fdiv_rn(__fadd_rn(target, -lp), denom), 0.0f), 1.0f);
            }
        }
        s_left[tid]  = l;
        s_right[tid] = rc;
        s_alpha[tid] = a;
    }
    __syncthreads();

    // ---- gather + blend the 24-bin trace; write to SMEM and GMEM ----
    const float* fb = feat + (size_t)b * T_LEN * F_DIM;
    const size_t trace_off = (size_t)B * ws * F_DIM;
    float* out_trace = out + trace_off + (size_t)b * BINS * F_DIM;
    #pragma unroll
    for (int i = 0; i < (BINS * F_DIM + NT - 1) / NT; i++) {
        int idx = tid + i * NT;
        if (idx < BINS * F_DIM) {
            int   j = idx / F_DIM, f = idx - j * F_DIM;
            float a  = s_alpha[j];
            float fl = fb[(size_t)s_left[j]  * F_DIM + f];
            float fr = fb[(size_t)s_right[j] * F_DIM + f];
            float val = __fadd_rn(__fmul_rn(fl, __fadd_rn(1.0f, -a)),
                                  __fmul_rn(fr, a));
            s_trace[idx]   = val;
            out_trace[idx] = val;
        }
    }
    __syncthreads();

    // ---- sample the trace at phase_ptr + linspace(0, HORIZON, ws) ----
    const float ph      = phase[b];
    const float delta_o = __fdiv_rn(HORIZON, (float)(ws - 1));
    float* out_sampled = out + (size_t)b * ws * F_DIM;
    for (int idx = tid; idx < ws * F_DIM; idx += NT) {
        int   i = idx / F_DIM, f = idx - i * F_DIM;
        float off    = (i == ws - 1) ? HORIZON : __fmul_rn((float)i, delta_o);
        float pos    = fminf(fmaxf(__fadd_rn(ph, off), 0.0f), 1.0f);
        float scaled = __fmul_rn(pos, (float)(BINS - 1));
        int   l = min(max((int)floorf(scaled), 0), BINS - 1);
        int   r = min(l + 1, BINS - 1);
        float a = __fadd_rn(scaled, -(float)l);
        float gl = s_trace[l * F_DIM + f];
        float gr = s_trace[r * F_DIM + f];
        out_sampled[idx] = __fadd_rn(__fmul_rn(gl, __fadd_rn(1.0f, -a)),
                                     __fmul_rn(gr, a));
    }

    // ---- run_mean ----
    if (tid == 0) {
        int rr = 0;
        #pragma unroll
        for (int w = 0; w < NW; w++) rr += s_wrises[w];
        float rm = (rr > 0) ? __fdiv_rn((float)total, fmaxf((float)rr, 1.0f)) : 0.0f;
        out[trace_off + (size_t)B * BINS * F_DIM + b] = rm;
    }
}

extern "C" void kernel_launch(void* const* d_in, const int* in_sizes, int n_in,
                              void* d_out, int out_size) {
    const float* feat = (const float*)d_in[0];

    // Bind mask/phase by SIZE, not position.
    const int*   mask;
    const float* phase;
    int B;
    if (in_sizes[1] > in_sizes[2]) {        // order: feat, mask, phase
        mask  = (const int*)d_in[1];
        phase = (const float*)d_in[2];
        B     = in_sizes[2];
    } else {                                 // order: feat, phase, mask
        phase = (const float*)d_in[1];
        mask  = (const int*)d_in[2];
        B     = in_sizes[1];
    }

    // Derive window_size from out_size = B*(ws*F + BINS*F + 1).
    const int ws = (out_size / B - 1) / F_DIM - BINS;

    float* out = (float*)d_out;
    rhythm_kernel<<<B, NT>>>(feat, mask, phase, out, ws);
}

// round 17
// speedup vs baseline: 1.1604x; 1.1604x over previous
#include <cuda_runtime.h>
#include <cuda_bf16.h>

#define T_LEN   8192
#define F_DIM   80
#define BINS    24
#define NT      1024
#define PER     (T_LEN / NT)     // 8
#define NW      (NT / 32)        // 32 warps
#define HORIZON 0.35f

__global__ __launch_bounds__(NT) void rhythm_kernel(
    const float* __restrict__ feat,
    const int*   __restrict__ mask,
    const float* __restrict__ phase,
    float*       __restrict__ out,
    const int    ws)
{
    const int b   = blockIdx.x;
    const int B   = gridDim.x;
    const int tid = threadIdx.x;

    __shared__ float s_trace[BINS * F_DIM];  // 7.5 KB
    __shared__ int   s_left[BINS], s_right[BINS];
    __shared__ float s_alpha[BINS];
    __shared__ int   s_cstar[BINS];
    __shared__ int   s_wsum[NW];             // inclusive-scanned warp sums
    __shared__ int   s_wrises[NW];

    // ---- blocked GMEM load: each thread reads its own 8 mask values ----
    const int* mb   = mask + (size_t)b * T_LEN;
    const int  base = tid * PER;
    int m[PER];
    {
        const int4* p4 = (const int4*)(mb + base);
        #pragma unroll
        for (int q = 0; q < PER / 4; q++) {
            int4 w = p4[q];
            m[4 * q + 0] = w.x; m[4 * q + 1] = w.y;
            m[4 * q + 2] = w.z; m[4 * q + 3] = w.w;
        }
    }
    const int prev0 = (tid == 0) ? 0 : mb[base - 1];

    // ---- rises + local inclusive scan (registers only) ----
    int v[PER];
    const int lane = tid & 31, warp = tid >> 5;
    int run;
    {
        int prev = prev0, rises = 0, r0 = 0;
        #pragma unroll
        for (int k = 0; k < PER; k++) {
            rises += (m[k] == 1 && prev == 0);
            prev   = m[k];
            r0    += m[k];
            v[k]   = r0;
        }
        run = r0;
        #pragma unroll
        for (int o = 16; o; o >>= 1) rises += __shfl_down_sync(0xffffffffu, rises, o);
        if (lane == 0) s_wrises[warp] = rises;
    }
    // warp-level inclusive scan of per-thread sums
    int x = run;
    #pragma unroll
    for (int o = 1; o < 32; o <<= 1) {
        int y = __shfl_up_sync(0xffffffffu, x, o);
        if (lane >= o) x += y;
    }
    if (lane == 31) s_wsum[warp] = x;
    __syncthreads();
    if (tid < NW) {
        int xx = s_wsum[tid];
        #pragma unroll
        for (int o = 1; o < NW; o <<= 1) {
            int y = __shfl_up_sync(0xffffffffu, xx, o);
            if (tid >= o) xx += y;
        }
        s_wsum[tid] = xx;                    // inclusive warp-prefix sums
    }
    __syncthreads();

    const int prefix = ((warp == 0) ? 0 : s_wsum[warp - 1]) + (x - run); // exclusive
    const int total  = s_wsum[NW - 1];
    const float maxtot      = fmaxf((float)total, 1.0f);
    const bool  use_uniform = (total <= 0);
    // XLA AlgebraicSimplifier: divide -> multiply by hoisted IEEE reciprocal.
    const float recip   = __fdiv_rn(1.0f, maxtot);
    const float delta_t = __fdiv_rn(1.0f, (float)(BINS - 1));

    // ---- Phase B: 24 threads compute c*_i = min{c : RN(c*recip) >= t_i} ----
    // p[k]=RN(csum[k]*recip) monotone in csum => right_i = first k with
    // csum[k] >= c*_i; csum steps 0/1 => csum at right-1/right = c*-1/c* exact.
    if (tid < BINS && !use_uniform) {
        const float target = (tid == BINS - 1) ? 1.0f
                           : __fmul_rn((float)tid, delta_t);
        int cb = (int)ceilf(__fmul_rn(target, maxtot)) - 3;
        if (cb < 0) cb = 0;
        int cstar = cb + 7;
        #pragma unroll 1
        for (int c = cb; c <= cb + 6; c++) {
            if (__fmul_rn((float)c, recip) >= target) { cstar = c; break; }
        }
        s_cstar[tid] = cstar;
        if (cstar <= 0)          s_right[tid] = 0;      // sole writer
        else if (cstar > total)  s_right[tid] = T_LEN;  // sole writer
    }
    __syncthreads();

    // ---- Phase C: cheap ownership scan (unique owner per bin writes) ----
    if (!use_uniform) {
        #pragma unroll 1
        for (int i = 0; i < BINS; i++) {
            const int cstar = s_cstar[i];               // broadcast LDS
            if (cstar >= 1 && cstar <= total &&
                prefix < cstar && cstar <= prefix + run) {
                const int need = cstar - prefix;
                int pos = PER - 1;
                #pragma unroll
                for (int k = PER - 1; k >= 0; k--) if (v[k] >= need) pos = k;
                s_right[i] = base + pos;
            }
        }
    }
    __syncthreads();

    // ---- per-bin left/right/alpha (24 threads) ----
    if (tid < BINS) {
        const float target = (tid == BINS - 1) ? 1.0f
                           : __fmul_rn((float)tid, delta_t);
        int right, l, rc;
        float a;
        if (use_uniform) {
            const float delta_u = __fdiv_rn(1.0f, (float)(T_LEN - 1));
            int lo = 0, hi = T_LEN;
            while (lo < hi) {
                int   mid = (lo + hi) >> 1;
                float p   = (mid == T_LEN - 1) ? 1.0f
                          : __fmul_rn((float)mid, delta_u);
                if (p >= target) hi = mid; else lo = mid + 1;
            }
            right = lo;
            if (right <= 0)          { l = 0;         rc = 0;         a = 0.0f; }
            else if (right >= T_LEN) { l = T_LEN - 1; rc = T_LEN - 1; a = 0.0f; }
            else {
                l  = right - 1;
                rc = right;
                float lp = (l  == T_LEN - 1) ? 1.0f : __fmul_rn((float)l,  delta_u);
                float rp = (rc == T_LEN - 1) ? 1.0f : __fmul_rn((float)rc, delta_u);
                float denom = fmaxf(fabsf(__fadd_rn(rp, -lp)), 1e-6f);
                a = fminf(fmaxf(__fdiv_rn(__fadd_rn(target, -lp), denom), 0.0f), 1.0f);
            }
        } else {
            right = s_right[tid];
            const int cstar = s_cstar[tid];
            if (right <= 0)          { l = 0;         rc = 0;         a = 0.0f; }
            else if (right >= T_LEN) { l = T_LEN - 1; rc = T_LEN - 1; a = 0.0f; }
            else {
                l  = right - 1;
                rc = right;
                float lp = __fmul_rn((float)(cstar - 1), recip);
                float rp = __fmul_rn((float)cstar,       recip);
                float denom = fmaxf(fabsf(__fadd_rn(rp, -lp)), 1e-6f);
                a = fminf(fmaxf(__fdiv_rn(__fadd_rn(target, -lp), denom), 0.0f), 1.0f);
            }
        }
        s_left[tid]  = l;
        s_right[tid] = rc;
        s_alpha[tid] = a;
    }
    __syncthreads();

    // ---- gather + blend the 24-bin trace; write to SMEM and GMEM ----
    const float* fb = feat + (size_t)b * T_LEN * F_DIM;
    const size_t trace_off = (size_t)B * ws * F_DIM;
    float* out_trace = out + trace_off + (size_t)b * BINS * F_DIM;
    #pragma unroll
    for (int i = 0; i < (BINS * F_DIM + NT - 1) / NT; i++) {
        int idx = tid + i * NT;
        if (idx < BINS * F_DIM) {
            int   j = idx / F_DIM, f = idx - j * F_DIM;
            float a  = s_alpha[j];
            float fl = fb[(size_t)s_left[j]  * F_DIM + f];
            float fr = fb[(size_t)s_right[j] * F_DIM + f];
            float val = __fadd_rn(__fmul_rn(fl, __fadd_rn(1.0f, -a)),
                                  __fmul_rn(fr, a));
            s_trace[idx]   = val;
            out_trace[idx] = val;
        }
    }
    __syncthreads();

    // ---- sample the trace at phase_ptr + linspace(0, HORIZON, ws) ----
    const float ph      = phase[b];
    const float delta_o = __fdiv_rn(HORIZON, (float)(ws - 1));
    float* out_sampled = out + (size_t)b * ws * F_DIM;
    for (int idx = tid; idx < ws * F_DIM; idx += NT) {
        int   i = idx / F_DIM, f = idx - i * F_DIM;
        float off    = (i == ws - 1) ? HORIZON : __fmul_rn((float)i, delta_o);
        float pos    = fminf(fmaxf(__fadd_rn(ph, off), 0.0f), 1.0f);
        float scaled = __fmul_rn(pos, (float)(BINS - 1));
        int   l = min(max((int)floorf(scaled), 0), BINS - 1);
        int   r = min(l + 1, BINS - 1);
        float a = __fadd_rn(scaled, -(float)l);
        float gl = s_trace[l * F_DIM + f];
        float gr = s_trace[r * F_DIM + f];
        out_sampled[idx] = __fadd_rn(__fmul_rn(gl, __fadd_rn(1.0f, -a)),
                                     __fmul_rn(gr, a));
    }

    // ---- run_mean ----
    if (tid == 0) {
        int rr = 0;
        #pragma unroll
        for (int w = 0; w < NW; w++) rr += s_wrises[w];
        float rm = (rr > 0) ? __fdiv_rn((float)total, fmaxf((float)rr, 1.0f)) : 0.0f;
        out[trace_off + (size_t)B * BINS * F_DIM + b] = rm;
    }
}

extern "C" void kernel_launch(void* const* d_in, const int* in_sizes, int n_in,
                              void* d_out, int out_size) {
    const float* feat = (const float*)d_in[0];

    // Bind mask/phase by SIZE, not position.
    const int*   mask;
    const float* phase;
    int B;
    if (in_sizes[1] > in_sizes[2]) {        // order: feat, mask, phase
        mask  = (const int*)d_in[1];
        phase = (const float*)d_in[2];
        B     = in_sizes[2];
    } else {                                 // order: feat, phase, mask
        phase = (const float*)d_in[1];
        mask  = (const int*)d_in[2];
        B     = in_sizes[1];
    }

    // Derive window_size from out_size = B*(ws*F + BINS*F + 1).
    const int ws = (out_size / B - 1) / F_DIM - BINS;

    float* out = (float*)d_out;
    rhythm_kernel<<<B, NT>>>(feat, mask, phase, out, ws);
}